// round 4
// baseline (speedup 1.0000x reference)
#include <cuda_runtime.h>
#include <math.h>

// ---------------------------------------------------------------------------
// GAT (2 layers) on GB300, round 2.
// - CSR build: memset + hist + ONE scan kernel (atomic block-base) + scatter
// - proj1: packed fma.rn.f32x2 (FFMA2) GEMM
// - agg1/agg2: one-pass online-softmax, 2-edges-per-iter accumulation
// ---------------------------------------------------------------------------

constexpr int N_NODES = 100000;
constexpr int N_EDGES = 1600000;
constexpr int IN_DIM  = 128;
constexpr int HEADS1  = 4;
constexpr int HIDDEN  = 64;     // HEADS1 * 16
constexpr int CLASSES = 16;
constexpr float NEG   = 0.2f;
constexpr float EPS_D = 1e-9f;

// Scratch (static device globals)
__device__ float g_h1[N_NODES * HIDDEN];
__device__ float g_s1src[N_NODES * HEADS1];
__device__ float g_s1dst[N_NODES * HEADS1];
__device__ float g_h2[N_NODES * CLASSES];
__device__ float g_s2src[N_NODES];
__device__ float g_s2dst[N_NODES];
__device__ int   g_deg[N_NODES + 1];        // [N_NODES] = global base counter
__device__ int   g_off[N_NODES];
__device__ int   g_cur[N_NODES];
__device__ int   g_srcsorted[N_EDGES];

__device__ __forceinline__ float lrelu(float x) { return fmaxf(x, NEG * x); }
__device__ __forceinline__ float elu(float x)   { return x > 0.f ? x : expm1f(x); }

__device__ __forceinline__ void fma2(unsigned long long& d,
                                     unsigned long long a, unsigned long long b) {
    asm("fma.rn.f32x2 %0, %1, %2, %0;" : "+l"(d) : "l"(a), "l"(b));
}
__device__ __forceinline__ unsigned long long dup2(float x) {
    unsigned long long r;
    asm("mov.b64 %0, {%1, %1};" : "=l"(r) : "f"(x));
    return r;
}
__device__ __forceinline__ float lo32(unsigned long long v) {
    return __uint_as_float((unsigned)(v & 0xffffffffULL));
}
__device__ __forceinline__ float hi32(unsigned long long v) {
    return __uint_as_float((unsigned)(v >> 32));
}

// ------------------------------ CSR build ----------------------------------

__global__ void hist_kernel(const int* __restrict__ rcv) {
    int i = blockIdx.x * blockDim.x + threadIdx.x;
    if (i < N_EDGES) atomicAdd(&g_deg[rcv[i]], 1);
}

// One-kernel scan: per-block inclusive scan, block claims its base atomically.
// Offsets are NOT monotonic across nodes; consumers use off + deg.
__global__ void scan_kernel() {
    __shared__ int s[256];
    __shared__ int sbase;
    int t = threadIdx.x;
    int i = blockIdx.x * 256 + t;
    int mine = (i < N_NODES) ? g_deg[i] : 0;
    s[t] = mine;
    __syncthreads();
    for (int o = 1; o < 256; o <<= 1) {
        int v = (t >= o) ? s[t - o] : 0;
        __syncthreads();
        s[t] += v;
        __syncthreads();
    }
    if (t == 0) sbase = atomicAdd(&g_deg[N_NODES], s[255]);
    __syncthreads();
    if (i < N_NODES) {
        int off = sbase + s[t] - mine;
        g_off[i] = off;
        g_cur[i] = off;
    }
}

__global__ void scatter_kernel(const int* __restrict__ snd, const int* __restrict__ rcv) {
    int i = blockIdx.x * blockDim.x + threadIdx.x;
    if (i < N_EDGES) {
        int p = atomicAdd(&g_cur[rcv[i]], 1);
        g_srcsorted[p] = snd[i];
    }
}

// ---------------------- Layer-1 projection (FFMA2 GEMM) --------------------

__global__ void __launch_bounds__(256) proj1_kernel(
    const float* __restrict__ x, const float* __restrict__ W1,
    const float* __restrict__ a1s_, const float* __restrict__ a1d_)
{
    __shared__ __align__(16) float Ws[IN_DIM * HIDDEN];   // [k][64], 32KB
    __shared__ float as[HIDDEN], ad[HIDDEN];
    int t = threadIdx.x;
    for (int i = t; i < HEADS1 * IN_DIM * 16; i += 256) {
        int h = i >> 11;
        int k = (i >> 4) & 127;
        int f = i & 15;
        Ws[k * HIDDEN + h * 16 + f] = W1[i];
    }
    if (t < HIDDEN) { as[t] = a1s_[t]; ad[t] = a1d_[t]; }
    __syncthreads();

    int node = blockIdx.x * 256 + t;
    if (node >= N_NODES) return;

    unsigned long long acc[HIDDEN / 2];      // 32 packed f32x2 accumulators
#pragma unroll
    for (int c = 0; c < HIDDEN / 2; c++) acc[c] = 0ULL;

    const float4* xr = (const float4*)(x + node * IN_DIM);
#pragma unroll 2
    for (int k4 = 0; k4 < IN_DIM / 4; k4++) {
        float4 xv = xr[k4];
#pragma unroll
        for (int kk = 0; kk < 4; kk++) {
            float xk = (kk == 0) ? xv.x : (kk == 1) ? xv.y : (kk == 2) ? xv.z : xv.w;
            unsigned long long x2 = dup2(xk);
            const ulonglong2* wrow = (const ulonglong2*)&Ws[(k4 * 4 + kk) * HIDDEN];
#pragma unroll
            for (int c4 = 0; c4 < HIDDEN / 4; c4++) {
                ulonglong2 wv = wrow[c4];
                fma2(acc[c4 * 2 + 0], x2, wv.x);
                fma2(acc[c4 * 2 + 1], x2, wv.y);
            }
        }
    }

    ulonglong2* h1r = (ulonglong2*)&g_h1[node * HIDDEN];
#pragma unroll
    for (int c4 = 0; c4 < HIDDEN / 4; c4++) {
        ulonglong2 v; v.x = acc[c4 * 2]; v.y = acc[c4 * 2 + 1];
        h1r[c4] = v;
    }

#pragma unroll
    for (int h = 0; h < HEADS1; h++) {
        float ss = 0.f, sd = 0.f;
#pragma unroll
        for (int c = 0; c < 8; c++) {   // 8 pairs = 16 cols of this head
            unsigned long long v = acc[h * 8 + c];
            float v0 = lo32(v), v1 = hi32(v);
            ss = fmaf(v0, as[h * 16 + c * 2], ss);
            ss = fmaf(v1, as[h * 16 + c * 2 + 1], ss);
            sd = fmaf(v0, ad[h * 16 + c * 2], sd);
            sd = fmaf(v1, ad[h * 16 + c * 2 + 1], sd);
        }
        g_s1src[node * HEADS1 + h] = ss;
        g_s1dst[node * HEADS1 + h] = sd;
    }
}

// -------------- Layer-1 aggregation (online softmax) + elu + proj2 ---------
// One warp per node. Online softmax: per 32-edge block compute block max,
// rescale running acc/denominator. Inner accumulate: 2 edges/iter, 16-lane
// halves, float4 h1 loads, halves combined via shfl_xor(16).

__global__ void __launch_bounds__(256) agg1_kernel(
    const float* __restrict__ W2, const float* __restrict__ a2src,
    const float* __restrict__ a2dst)
{
    __shared__ float W2s[HIDDEN * CLASSES];
    __shared__ float a2ss[CLASSES], a2ds[CLASSES];
    __shared__ float alphas[8][128];
    __shared__ int   snds[8][32];

    int t = threadIdx.x;
    for (int i = t; i < HIDDEN * CLASSES; i += 256) W2s[i] = W2[i];
    if (t < CLASSES) { a2ss[t] = a2src[t]; a2ds[t] = a2dst[t]; }
    __syncthreads();

    int lane = t & 31, wl = t >> 5;
    int node = blockIdx.x * 8 + wl;
    if (node >= N_NODES) return;

    int off0 = g_off[node];
    int deg  = g_deg[node];
    int off1 = off0 + deg;
    float4 sdst = *(const float4*)&g_s1dst[node * 4];

    int half = lane >> 4;        // which edge of the pair
    int hl   = lane & 15;        // col-quad index: cols hl*4 .. hl*4+3
    int hsel = hl >> 2;          // head of my 4 cols

    float4 runm = make_float4(-1e30f, -1e30f, -1e30f, -1e30f);
    float4 asum = make_float4(0.f, 0.f, 0.f, 0.f);
    float4 acc  = make_float4(0.f, 0.f, 0.f, 0.f);

    for (int b = off0; b < off1; b += 32) {
        int i = b + lane;
        int cnt = min(32, off1 - b);
        int s = 0;
        float4 e = make_float4(-1e30f, -1e30f, -1e30f, -1e30f);
        if (i < off1) {
            s = g_srcsorted[i];
            float4 ss = *(const float4*)&g_s1src[s * 4];
            e.x = lrelu(ss.x + sdst.x);
            e.y = lrelu(ss.y + sdst.y);
            e.z = lrelu(ss.z + sdst.z);
            e.w = lrelu(ss.w + sdst.w);
        }
        // block max
        float4 bm = e;
#pragma unroll
        for (int o = 16; o; o >>= 1) {
            bm.x = fmaxf(bm.x, __shfl_xor_sync(0xffffffffu, bm.x, o));
            bm.y = fmaxf(bm.y, __shfl_xor_sync(0xffffffffu, bm.y, o));
            bm.z = fmaxf(bm.z, __shfl_xor_sync(0xffffffffu, bm.z, o));
            bm.w = fmaxf(bm.w, __shfl_xor_sync(0xffffffffu, bm.w, o));
        }
        float4 newm = make_float4(fmaxf(runm.x, bm.x), fmaxf(runm.y, bm.y),
                                  fmaxf(runm.z, bm.z), fmaxf(runm.w, bm.w));
        float4 sc = make_float4(__expf(runm.x - newm.x), __expf(runm.y - newm.y),
                                __expf(runm.z - newm.z), __expf(runm.w - newm.w));
        asum.x *= sc.x; asum.y *= sc.y; asum.z *= sc.z; asum.w *= sc.w;
        float mysc = (hsel == 0) ? sc.x : (hsel == 1) ? sc.y : (hsel == 2) ? sc.z : sc.w;
        acc.x *= mysc; acc.y *= mysc; acc.z *= mysc; acc.w *= mysc;

        float4 al = make_float4(0.f, 0.f, 0.f, 0.f);
        if (i < off1) {
            al.x = __expf(e.x - newm.x);
            al.y = __expf(e.y - newm.y);
            al.z = __expf(e.z - newm.z);
            al.w = __expf(e.w - newm.w);
            asum.x += al.x; asum.y += al.y; asum.z += al.z; asum.w += al.w;
        }
        snds[wl][lane] = s;
        *(float4*)&alphas[wl][lane * 4] = al;
        __syncwarp();
        for (int j = 0; j < cnt; j += 2) {
            int jj = j + half;                    // jj<=31; al=0 beyond cnt
            float a = alphas[wl][jj * 4 + hsel];
            int sj = snds[wl][jj];
            float4 hv = *(const float4*)&g_h1[sj * HIDDEN + hl * 4];
            acc.x = fmaf(a, hv.x, acc.x);
            acc.y = fmaf(a, hv.y, acc.y);
            acc.z = fmaf(a, hv.z, acc.z);
            acc.w = fmaf(a, hv.w, acc.w);
        }
        __syncwarp();
        runm = newm;
    }
    // combine halves, reduce denominator
    acc.x += __shfl_xor_sync(0xffffffffu, acc.x, 16);
    acc.y += __shfl_xor_sync(0xffffffffu, acc.y, 16);
    acc.z += __shfl_xor_sync(0xffffffffu, acc.z, 16);
    acc.w += __shfl_xor_sync(0xffffffffu, acc.w, 16);
#pragma unroll
    for (int o = 16; o; o >>= 1) {
        asum.x += __shfl_xor_sync(0xffffffffu, asum.x, o);
        asum.y += __shfl_xor_sync(0xffffffffu, asum.y, o);
        asum.z += __shfl_xor_sync(0xffffffffu, asum.z, o);
        asum.w += __shfl_xor_sync(0xffffffffu, asum.w, o);
    }
    float den = (hsel == 0) ? asum.x : (hsel == 1) ? asum.y : (hsel == 2) ? asum.z : asum.w;
    float inv = 1.0f / (den + EPS_D);

    // stage elu'd row (lanes 0-15 hold the full 64-col row as float4s)
    if (half == 0) {
        float4 r;
        r.x = elu(acc.x * inv); r.y = elu(acc.y * inv);
        r.z = elu(acc.z * inv); r.w = elu(acc.w * inv);
        *(float4*)&alphas[wl][hl * 4] = r;
    }
    __syncwarp();
    if (lane < CLASSES) {
        float tv = 0.f;
#pragma unroll
        for (int k = 0; k < HIDDEN; k++)
            tv = fmaf(alphas[wl][k], W2s[k * CLASSES + lane], tv);
        g_h2[node * CLASSES + lane] = tv;
        float ps = tv * a2ss[lane];
        float pd = tv * a2ds[lane];
#pragma unroll
        for (int o = 8; o; o >>= 1) {
            ps += __shfl_down_sync(0x0000ffffu, ps, o);
            pd += __shfl_down_sync(0x0000ffffu, pd, o);
        }
        if (lane == 0) { g_s2src[node] = ps; g_s2dst[node] = pd; }
    }
}

// ------------------------- Layer-2 aggregation -----------------------------

__global__ void __launch_bounds__(256) agg2_kernel(float* __restrict__ out)
{
    __shared__ float alphas[8][32];
    __shared__ int   snds[8][32];
    int t = threadIdx.x, lane = t & 31, wl = t >> 5;
    int node = blockIdx.x * 8 + wl;
    if (node >= N_NODES) return;

    int off0 = g_off[node];
    int deg  = g_deg[node];
    int off1 = off0 + deg;
    float sd = g_s2dst[node];

    int half = lane >> 4;
    int fcol = lane & 15;

    float runm = -1e30f, asum = 0.f, acc = 0.f;
    for (int b = off0; b < off1; b += 32) {
        int i = b + lane;
        int cnt = min(32, off1 - b);
        int s = 0;
        float e = -1e30f;
        if (i < off1) {
            s = g_srcsorted[i];
            e = lrelu(g_s2src[s] + sd);
        }
        float bm = e;
#pragma unroll
        for (int o = 16; o; o >>= 1) bm = fmaxf(bm, __shfl_xor_sync(0xffffffffu, bm, o));
        float newm = fmaxf(runm, bm);
        float sc = __expf(runm - newm);
        acc *= sc; asum *= sc;
        float al = 0.f;
        if (i < off1) { al = __expf(e - newm); asum += al; }
        snds[wl][lane] = s;
        alphas[wl][lane] = al;
        __syncwarp();
        for (int j = 0; j < cnt; j += 2) {
            int jj = j + half;
            float a = alphas[wl][jj];
            int sj = snds[wl][jj];
            acc = fmaf(a, g_h2[sj * CLASSES + fcol], acc);
        }
        __syncwarp();
        runm = newm;
    }
    acc += __shfl_xor_sync(0xffffffffu, acc, 16);
#pragma unroll
    for (int o = 16; o; o >>= 1) asum += __shfl_xor_sync(0xffffffffu, asum, o);
    if (lane < CLASSES) out[node * CLASSES + lane] = acc / (asum + EPS_D);
}

// ------------------------------- launch ------------------------------------

extern "C" void kernel_launch(void* const* d_in, const int* in_sizes, int n_in,
                              void* d_out, int out_size)
{
    const float* x   = (const float*)d_in[0];
    const int*   snd = (const int*)  d_in[1];
    const int*   rcv = (const int*)  d_in[2];
    const float* W1  = (const float*)d_in[3];
    const float* a1s = (const float*)d_in[4];
    const float* a1d = (const float*)d_in[5];
    const float* W2  = (const float*)d_in[6];
    const float* a2s = (const float*)d_in[7];
    const float* a2d = (const float*)d_in[8];
    float* out = (float*)d_out;

    void* degptr = nullptr;
    cudaGetSymbolAddress(&degptr, g_deg);
    cudaMemsetAsync(degptr, 0, (N_NODES + 1) * sizeof(int), 0);

    const int nb_nodes = (N_NODES + 255) / 256;   // 391
    const int nb_edges = (N_EDGES + 255) / 256;   // 6250
    const int nb_warp8 = (N_NODES + 7) / 8;       // 12500

    hist_kernel<<<nb_edges, 256>>>(rcv);
    scan_kernel<<<nb_nodes, 256>>>();
    scatter_kernel<<<nb_edges, 256>>>(snd, rcv);

    proj1_kernel<<<nb_nodes, 256>>>(x, W1, a1s, a1d);
    agg1_kernel<<<nb_warp8, 256>>>(W2, a2s, a2d);
    agg2_kernel<<<nb_warp8, 256>>>(out);
}